// round 15
// baseline (speedup 1.0000x reference)
#include <cuda_runtime.h>

// Problem constants (fixed by the dataset)
#define NN   50000
#define RR   8
#define HH   64
#define CC   16
#define EE   1600000
#define TT   8192
#define KDIM (RR*HH + HH)   // 576: 8 relation-aggregates + h1 (for root2)

// ---------------- device scratch (no allocations allowed) ----------------
__device__ int      g_cnt[NN*RR];        // edges per (dst, rel)
__device__ int      g_off[NN];           // start offset of dst's segment
__device__ int      g_off2[NN*RR];       // start offset of each (dst, rel) sub-segment
__device__ unsigned g_packed[EE];        // (seg<<13) | rank  (seg = dst*8+rel)
__device__ int      g_ctr;               // global offset reservation counter
__device__ unsigned g_sorted[EE];        // (rel<<16)|src, grouped by (dst, rel)
__device__ float    g_h1[NN*HH];         // conv1 output
__device__ float    g_A[TT*KDIM];        // conv2 LHS: [acc_r0..acc_r7 | h1]

// ---------------- K0: zero counters ----------------
__global__ void k_zero() {
    int i = blockIdx.x*blockDim.x + threadIdx.x;
    if (i*4 < NN*RR) ((int4*)g_cnt)[i] = make_int4(0,0,0,0);
    if (i == 0) g_ctr = 0;
}

// ---------------- K1: histogram per (dst, rel) + packed (seg, rank) ----------------
__global__ void __launch_bounds__(256) k_hist(const int* __restrict__ ei,
                                              const int* __restrict__ et) {
    int e4 = (blockIdx.x*blockDim.x + threadIdx.x) * 4;
    if (e4 >= EE) return;
    int4 d = *(const int4*)(ei + EE + e4);
    int4 r = *(const int4*)(et + e4);
    int s0 = d.x*RR + r.x;
    int s1 = d.y*RR + r.y;
    int s2 = d.z*RR + r.z;
    int s3 = d.w*RR + r.w;
    uint4 pk;
    pk.x = ((unsigned)s0 << 13) | (unsigned)atomicAdd(&g_cnt[s0], 1);
    pk.y = ((unsigned)s1 << 13) | (unsigned)atomicAdd(&g_cnt[s1], 1);
    pk.z = ((unsigned)s2 << 13) | (unsigned)atomicAdd(&g_cnt[s2], 1);
    pk.w = ((unsigned)s3 << 13) | (unsigned)atomicAdd(&g_cnt[s3], 1);
    *(uint4*)(g_packed + e4) = pk;
}

// ---------------- K2: reserve contiguous segment per dst + per-rel sub-offsets ----------------
__global__ void k_offsets() {
    int v = blockIdx.x*blockDim.x + threadIdx.x;
    int lane = threadIdx.x & 31;
    int cnt[RR];
    int deg = 0;
    if (v < NN) {
        int4 a = *(const int4*)&g_cnt[v*RR];
        int4 b = *(const int4*)&g_cnt[v*RR + 4];
        cnt[0]=a.x; cnt[1]=a.y; cnt[2]=a.z; cnt[3]=a.w;
        cnt[4]=b.x; cnt[5]=b.y; cnt[6]=b.z; cnt[7]=b.w;
        #pragma unroll
        for (int r = 0; r < RR; r++) deg += cnt[r];
    }
    // warp inclusive scan
    int x = deg;
    #pragma unroll
    for (int d = 1; d < 32; d <<= 1) {
        int y = __shfl_up_sync(0xffffffffu, x, d);
        if (lane >= d) x += y;
    }
    int total = __shfl_sync(0xffffffffu, x, 31);
    int base = 0;
    if (lane == 31) base = atomicAdd(&g_ctr, total);
    base = __shfl_sync(0xffffffffu, base, 31);
    if (v < NN) {
        int off = base + x - deg;
        g_off[v] = off;
        int p = off;
        #pragma unroll
        for (int r = 0; r < RR; r++) { g_off2[v*RR + r] = p; p += cnt[r]; }
    }
}

// ---------------- K3: scatter edges (NO atomics; 4 edges/thread, 8 B/edge input) ----------------
__global__ void __launch_bounds__(256) k_scatter(const int* __restrict__ ei) {
    int e4 = (blockIdx.x*blockDim.x + threadIdx.x) * 4;
    if (e4 >= EE) return;
    uint4 p = *(const uint4*)(g_packed + e4);
    int4  s = *(const int4*)(ei + e4);
    unsigned pk[4] = {p.x, p.y, p.z, p.w};
    int      sr[4] = {s.x, s.y, s.z, s.w};
    int pos[4];
    #pragma unroll
    for (int j = 0; j < 4; j++)
        pos[j] = g_off2[pk[j] >> 13] + (int)(pk[j] & 8191u);
    #pragma unroll
    for (int j = 0; j < 4; j++) {
        unsigned rel = (pk[j] >> 13) & 7u;
        g_sorted[pos[j]] = (rel << 16) | (unsigned)sr[j];
    }
}

// ---------------- K4: conv1 — warp per dst, gather weight1 rows (unroll 8) ----------------
__global__ void __launch_bounds__(256) k_conv1(const float* __restrict__ w1,
                                               const float* __restrict__ root1,
                                               const float* __restrict__ bias1) {
    __shared__ float sInv[8][RR];
    int warp = threadIdx.x >> 5;
    int lane = threadIdx.x & 31;
    int dst = blockIdx.x*8 + warp;
    if (dst >= NN) return;

    int c = 0;
    if (lane < RR) {
        c = g_cnt[dst*RR + lane];
        sInv[warp][lane] = 1.0f / (float)max(c, 1);
    }
    int d = (lane < RR) ? c : 0;
    #pragma unroll
    for (int s = 16; s; s >>= 1) d += __shfl_xor_sync(0xffffffffu, d, s);
    int deg = d;
    __syncwarp();

    int off = g_off[dst];
    float2 acc = make_float2(0.f, 0.f);
    int i = 0;
    for (; i + 8 <= deg; i += 8) {
        unsigned u[8];
        #pragma unroll
        for (int j = 0; j < 8; j++) u[j] = g_sorted[off + i + j];
        float2 wv[8];
        #pragma unroll
        for (int j = 0; j < 8; j++) {
            int rel = (int)(u[j] >> 16), src = (int)(u[j] & 0xffffu);
            wv[j] = *((const float2*)(w1 + rel*(NN*HH) + src*HH) + lane);
        }
        #pragma unroll
        for (int j = 0; j < 8; j++) {
            float s = sInv[warp][u[j] >> 16];
            acc.x = fmaf(s, wv[j].x, acc.x);
            acc.y = fmaf(s, wv[j].y, acc.y);
        }
    }
    if (i + 4 <= deg) {
        unsigned u[4];
        #pragma unroll
        for (int j = 0; j < 4; j++) u[j] = g_sorted[off + i + j];
        float2 wv[4];
        #pragma unroll
        for (int j = 0; j < 4; j++) {
            int rel = (int)(u[j] >> 16), src = (int)(u[j] & 0xffffu);
            wv[j] = *((const float2*)(w1 + rel*(NN*HH) + src*HH) + lane);
        }
        #pragma unroll
        for (int j = 0; j < 4; j++) {
            float s = sInv[warp][u[j] >> 16];
            acc.x = fmaf(s, wv[j].x, acc.x);
            acc.y = fmaf(s, wv[j].y, acc.y);
        }
        i += 4;
    }
    for (; i < deg; i++) {
        unsigned u = g_sorted[off + i];
        int rel = (int)(u >> 16), src = (int)(u & 0xffffu);
        float2 wv = *((const float2*)(w1 + rel*(NN*HH) + src*HH) + lane);
        float s = sInv[warp][rel];
        acc.x = fmaf(s, wv.x, acc.x);
        acc.y = fmaf(s, wv.y, acc.y);
    }

    float2 rt = *((const float2*)(root1 + dst*HH) + lane);
    float2 bb = *((const float2*)bias1 + lane);
    float hx = acc.x + rt.x + bb.x;
    float hy = acc.y + rt.y + bb.y;
    hx = hx > 0.f ? hx : expm1f(hx);
    hy = hy > 0.f ? hy : expm1f(hy);
    float2 hv = make_float2(hx, hy);
    *((float2*)(g_h1 + dst*HH) + lane) = hv;
    if (dst < TT)   // stash h1 row as last 64 cols of A (root2 term of conv2)
        *((float2*)(g_A + dst*KDIM + RR*HH) + lane) = hv;
}

// ---------------- K5: conv2 aggregation — per-relation runs (edges are rel-sorted) ----------------
__global__ void __launch_bounds__(256) k_conv2agg() {
    int lane = threadIdx.x & 31;
    int dst = blockIdx.x*8 + (threadIdx.x >> 5);   // grid sized so dst < TT exactly

    int cnt = 0;
    float inv = 1.0f;
    if (lane < RR) {
        cnt = g_cnt[dst*RR + lane];
        inv = 1.0f / (float)max(cnt, 1);
    }

    int ptr = g_off[dst];
    #pragma unroll
    for (int r = 0; r < RR; r++) {
        int   c = __shfl_sync(0xffffffffu, cnt, r);
        float s = __shfl_sync(0xffffffffu, inv, r);
        float2 sum = make_float2(0.f, 0.f);
        int i = 0;
        for (; i + 4 <= c; i += 4) {
            unsigned u[4];
            #pragma unroll
            for (int j = 0; j < 4; j++) u[j] = g_sorted[ptr + i + j];
            float2 hv[4];
            #pragma unroll
            for (int j = 0; j < 4; j++)
                hv[j] = *((const float2*)(g_h1 + (int)(u[j] & 0xffffu)*HH) + lane);
            #pragma unroll
            for (int j = 0; j < 4; j++) { sum.x += hv[j].x; sum.y += hv[j].y; }
        }
        for (; i < c; i++) {
            unsigned u = g_sorted[ptr + i];
            float2 h = *((const float2*)(g_h1 + (int)(u & 0xffffu)*HH) + lane);
            sum.x += h.x; sum.y += h.y;
        }
        ptr += c;
        *((float2*)(g_A + dst*KDIM + r*HH) + lane) = make_float2(sum.x*s, sum.y*s);
    }
}

// ---------------- K6: fused h2 = elu(A @ [w2;root2] + b2), out = h2 @ lin_w + lin_b ----------------
__global__ void __launch_bounds__(256) k_gemm(const float* __restrict__ w2,
                                              const float* __restrict__ root2,
                                              const float* __restrict__ bias2,
                                              const float* __restrict__ lw,
                                              const float* __restrict__ lb,
                                              float* __restrict__ out) {
    __shared__ float sA[64][33];       // A[m][k]
    __shared__ float sB[32*64];        // B[k][n], stride 64
    __shared__ float sH[64][65];       // h2 tile
    __shared__ float sW[HH*CC];        // lin_w
    int tid = threadIdx.x;
    int tx = tid & 15;                 // n dir: 4 cols each -> 64
    int ty = tid >> 4;                 // m dir: 4 rows each -> 64
    int m0 = blockIdx.x * 64;

    // preload lin_w (consumed after the k-loop; first __syncthreads covers it)
    *(float4*)&sW[tid*4] = *(const float4*)(lw + tid*4);

    float acc[4][4] = {};

    for (int kk0 = 0; kk0 < KDIM; kk0 += 32) {
        #pragma unroll
        for (int rep = 0; rep < 2; rep++) {
            int id = tid + rep*256;
            int row = id >> 3;             // 0..63
            int q = id & 7;                // 0..7
            float4 v = *(const float4*)(g_A + (m0 + row)*KDIM + kk0 + q*4);
            sA[row][q*4+0] = v.x; sA[row][q*4+1] = v.y;
            sA[row][q*4+2] = v.z; sA[row][q*4+3] = v.w;
        }
        #pragma unroll
        for (int rep = 0; rep < 2; rep++) {
            int id = tid + rep*256;
            int krow = id >> 4;            // 0..31
            int q = id & 15;               // 0..15
            int kk = kk0 + krow;
            const float* brow = (kk < RR*HH) ? (w2 + kk*HH) : (root2 + (kk - RR*HH)*HH);
            *(float4*)&sB[krow*64 + q*4] = *(const float4*)(brow + q*4);
        }
        __syncthreads();
        #pragma unroll
        for (int k = 0; k < 32; k++) {
            float a0 = sA[ty*4+0][k];
            float a1 = sA[ty*4+1][k];
            float a2 = sA[ty*4+2][k];
            float a3 = sA[ty*4+3][k];
            float4 b = *(const float4*)&sB[k*64 + tx*4];
            acc[0][0] = fmaf(a0,b.x,acc[0][0]); acc[0][1] = fmaf(a0,b.y,acc[0][1]);
            acc[0][2] = fmaf(a0,b.z,acc[0][2]); acc[0][3] = fmaf(a0,b.w,acc[0][3]);
            acc[1][0] = fmaf(a1,b.x,acc[1][0]); acc[1][1] = fmaf(a1,b.y,acc[1][1]);
            acc[1][2] = fmaf(a1,b.z,acc[1][2]); acc[1][3] = fmaf(a1,b.w,acc[1][3]);
            acc[2][0] = fmaf(a2,b.x,acc[2][0]); acc[2][1] = fmaf(a2,b.y,acc[2][1]);
            acc[2][2] = fmaf(a2,b.z,acc[2][2]); acc[2][3] = fmaf(a2,b.w,acc[2][3]);
            acc[3][0] = fmaf(a3,b.x,acc[3][0]); acc[3][1] = fmaf(a3,b.y,acc[3][1]);
            acc[3][2] = fmaf(a3,b.z,acc[3][2]); acc[3][3] = fmaf(a3,b.w,acc[3][3]);
        }
        __syncthreads();
    }

    // bias + elu into sH
    float4 bb = *(const float4*)(bias2 + tx*4);
    #pragma unroll
    for (int i = 0; i < 4; i++) {
        float v0 = acc[i][0] + bb.x;
        float v1 = acc[i][1] + bb.y;
        float v2 = acc[i][2] + bb.z;
        float v3 = acc[i][3] + bb.w;
        v0 = v0 > 0.f ? v0 : expm1f(v0);
        v1 = v1 > 0.f ? v1 : expm1f(v1);
        v2 = v2 > 0.f ? v2 : expm1f(v2);
        v3 = v3 > 0.f ? v3 : expm1f(v3);
        sH[ty*4+i][tx*4+0] = v0;
        sH[ty*4+i][tx*4+1] = v1;
        sH[ty*4+i][tx*4+2] = v2;
        sH[ty*4+i][tx*4+3] = v3;
    }
    __syncthreads();

    // head: out[m0+r, c] = sum_k sH[r][k] * lin_w[k][c] + lin_b[c]
    int r = tid >> 2;                  // 0..63
    int c0 = (tid & 3) * 4;            // 0,4,8,12
    float4 lbv = *(const float4*)(lb + c0);
    float s0 = lbv.x, s1 = lbv.y, s2 = lbv.z, s3 = lbv.w;
    #pragma unroll
    for (int k = 0; k < HH; k++) {
        float h = sH[r][k];
        float4 w = *(const float4*)&sW[k*CC + c0];
        s0 = fmaf(h, w.x, s0);
        s1 = fmaf(h, w.y, s1);
        s2 = fmaf(h, w.z, s2);
        s3 = fmaf(h, w.w, s3);
    }
    *(float4*)(out + (m0 + r)*CC + c0) = make_float4(s0, s1, s2, s3);
}

// ---------------- launcher ----------------
extern "C" void kernel_launch(void* const* d_in, const int* in_sizes, int n_in,
                              void* d_out, int out_size) {
    const int*   ei    = (const int*)d_in[0];    // edge_index [2,E]
    const int*   et    = (const int*)d_in[1];    // edge_type [E]
    // d_in[2] = num_target (shape known statically; out_size confirms T*C)
    const float* w1    = (const float*)d_in[3];  // [R,N,H]
    const float* root1 = (const float*)d_in[4];  // [N,H]
    const float* b1    = (const float*)d_in[5];  // [H]
    const float* w2    = (const float*)d_in[6];  // [R,H,H]
    const float* root2 = (const float*)d_in[7];  // [H,H]
    const float* b2    = (const float*)d_in[8];  // [H]
    const float* lw    = (const float*)d_in[9];  // [H,C]
    const float* lb    = (const float*)d_in[10]; // [C]
    float* out = (float*)d_out;
    (void)in_sizes; (void)n_in; (void)out_size;

    k_zero    <<<(NN*RR/4 + 255)/256, 256>>>();
    k_hist    <<<(EE/4 + 255)/256,    256>>>(ei, et);
    k_offsets <<<(NN + 255)/256,      256>>>();
    k_scatter <<<(EE/4 + 255)/256,    256>>>(ei);
    k_conv1   <<<(NN + 7)/8,          256>>>(w1, root1, b1);
    k_conv2agg<<<TT/8,                256>>>();
    k_gemm    <<<TT/64,               256>>>(w2, root2, b2, lw, lb, out);
}

// round 16
// speedup vs baseline: 1.2977x; 1.2977x over previous
#include <cuda_runtime.h>

// Problem constants (fixed by the dataset)
#define NN   50000
#define RR   8
#define HH   64
#define CC   16
#define EE   1600000
#define TT   8192
#define KDIM (RR*HH + HH)   // 576: 8 relation-aggregates + h1 (for root2)

// ---------------- device scratch (no allocations allowed) ----------------
__device__ int      g_cnt[NN*RR];        // edges per (dst, rel)
__device__ int      g_off[NN];           // start offset of dst's segment
__device__ int      g_off2[NN*RR];       // cursor: start offset of each (dst, rel) sub-segment
__device__ int      g_ctr;               // global offset reservation counter
__device__ unsigned g_sorted[EE];        // (rel<<16)|src, grouped by (dst, rel)
__device__ float    g_h1[NN*HH];         // conv1 output
__device__ float    g_A[TT*KDIM];        // conv2 LHS: [acc_r0..acc_r7 | h1]

// ---------------- K0: zero counters ----------------
__global__ void k_zero() {
    int i = blockIdx.x*blockDim.x + threadIdx.x;
    if (i*4 < NN*RR) ((int4*)g_cnt)[i] = make_int4(0,0,0,0);
    if (i == 0) g_ctr = 0;
}

// ---------------- K1: pure histogram per (dst, rel) — fire-and-forget RED ----------------
__global__ void __launch_bounds__(256) k_hist(const int* __restrict__ ei,
                                              const int* __restrict__ et) {
    int e4 = (blockIdx.x*blockDim.x + threadIdx.x) * 4;
    if (e4 >= EE) return;
    int4 d = __ldcs((const int4*)(ei + EE + e4));
    int4 r = __ldcs((const int4*)(et + e4));
    atomicAdd(&g_cnt[d.x*RR + r.x], 1);   // result unused -> RED (no return latency)
    atomicAdd(&g_cnt[d.y*RR + r.y], 1);
    atomicAdd(&g_cnt[d.z*RR + r.z], 1);
    atomicAdd(&g_cnt[d.w*RR + r.w], 1);
}

// ---------------- K2: reserve contiguous segment per dst + per-rel sub-cursors ----------------
__global__ void k_offsets() {
    int v = blockIdx.x*blockDim.x + threadIdx.x;
    int lane = threadIdx.x & 31;
    int cnt[RR];
    int deg = 0;
    if (v < NN) {
        int4 a = *(const int4*)&g_cnt[v*RR];
        int4 b = *(const int4*)&g_cnt[v*RR + 4];
        cnt[0]=a.x; cnt[1]=a.y; cnt[2]=a.z; cnt[3]=a.w;
        cnt[4]=b.x; cnt[5]=b.y; cnt[6]=b.z; cnt[7]=b.w;
        #pragma unroll
        for (int r = 0; r < RR; r++) deg += cnt[r];
    }
    // warp inclusive scan
    int x = deg;
    #pragma unroll
    for (int d = 1; d < 32; d <<= 1) {
        int y = __shfl_up_sync(0xffffffffu, x, d);
        if (lane >= d) x += y;
    }
    int total = __shfl_sync(0xffffffffu, x, 31);
    int base = 0;
    if (lane == 31) base = atomicAdd(&g_ctr, total);
    base = __shfl_sync(0xffffffffu, base, 31);
    if (v < NN) {
        int off = base + x - deg;
        g_off[v] = off;
        int p = off;
        #pragma unroll
        for (int r = 0; r < RR; r++) { g_off2[v*RR + r] = p; p += cnt[r]; }
    }
}

// ---------------- K3: scatter edges via atomic cursor (single pass, 12 B/edge in) ----------------
__global__ void __launch_bounds__(256) k_scatter(const int* __restrict__ ei,
                                                 const int* __restrict__ et) {
    int e4 = (blockIdx.x*blockDim.x + threadIdx.x) * 4;
    if (e4 >= EE) return;
    int4 s = __ldcs((const int4*)(ei + e4));
    int4 d = __ldcs((const int4*)(ei + EE + e4));
    int4 r = __ldcs((const int4*)(et + e4));
    int seg[4] = {d.x*RR + r.x, d.y*RR + r.y, d.z*RR + r.z, d.w*RR + r.w};
    int pos[4];
    #pragma unroll
    for (int j = 0; j < 4; j++) pos[j] = atomicAdd(&g_off2[seg[j]], 1);
    g_sorted[pos[0]] = ((unsigned)r.x << 16) | (unsigned)s.x;
    g_sorted[pos[1]] = ((unsigned)r.y << 16) | (unsigned)s.y;
    g_sorted[pos[2]] = ((unsigned)r.z << 16) | (unsigned)s.z;
    g_sorted[pos[3]] = ((unsigned)r.w << 16) | (unsigned)s.w;
}

// ---------------- K4: conv1 — warp per dst, gather weight1 rows (unroll 8) ----------------
__global__ void __launch_bounds__(256) k_conv1(const float* __restrict__ w1,
                                               const float* __restrict__ root1,
                                               const float* __restrict__ bias1) {
    __shared__ float sInv[8][RR];
    int warp = threadIdx.x >> 5;
    int lane = threadIdx.x & 31;
    int dst = blockIdx.x*8 + warp;
    if (dst >= NN) return;

    int c = 0;
    if (lane < RR) {
        c = g_cnt[dst*RR + lane];
        sInv[warp][lane] = 1.0f / (float)max(c, 1);
    }
    int d = (lane < RR) ? c : 0;
    #pragma unroll
    for (int s = 16; s; s >>= 1) d += __shfl_xor_sync(0xffffffffu, d, s);
    int deg = d;
    __syncwarp();

    int off = g_off[dst];
    float2 acc = make_float2(0.f, 0.f);
    int i = 0;
    for (; i + 8 <= deg; i += 8) {
        unsigned u[8];
        #pragma unroll
        for (int j = 0; j < 8; j++) u[j] = g_sorted[off + i + j];
        float2 wv[8];
        #pragma unroll
        for (int j = 0; j < 8; j++) {
            int rel = (int)(u[j] >> 16), src = (int)(u[j] & 0xffffu);
            wv[j] = *((const float2*)(w1 + rel*(NN*HH) + src*HH) + lane);
        }
        #pragma unroll
        for (int j = 0; j < 8; j++) {
            float s = sInv[warp][u[j] >> 16];
            acc.x = fmaf(s, wv[j].x, acc.x);
            acc.y = fmaf(s, wv[j].y, acc.y);
        }
    }
    if (i + 4 <= deg) {
        unsigned u[4];
        #pragma unroll
        for (int j = 0; j < 4; j++) u[j] = g_sorted[off + i + j];
        float2 wv[4];
        #pragma unroll
        for (int j = 0; j < 4; j++) {
            int rel = (int)(u[j] >> 16), src = (int)(u[j] & 0xffffu);
            wv[j] = *((const float2*)(w1 + rel*(NN*HH) + src*HH) + lane);
        }
        #pragma unroll
        for (int j = 0; j < 4; j++) {
            float s = sInv[warp][u[j] >> 16];
            acc.x = fmaf(s, wv[j].x, acc.x);
            acc.y = fmaf(s, wv[j].y, acc.y);
        }
        i += 4;
    }
    for (; i < deg; i++) {
        unsigned u = g_sorted[off + i];
        int rel = (int)(u >> 16), src = (int)(u & 0xffffu);
        float2 wv = *((const float2*)(w1 + rel*(NN*HH) + src*HH) + lane);
        float s = sInv[warp][rel];
        acc.x = fmaf(s, wv.x, acc.x);
        acc.y = fmaf(s, wv.y, acc.y);
    }

    float2 rt = *((const float2*)(root1 + dst*HH) + lane);
    float2 bb = *((const float2*)bias1 + lane);
    float hx = acc.x + rt.x + bb.x;
    float hy = acc.y + rt.y + bb.y;
    hx = hx > 0.f ? hx : expm1f(hx);
    hy = hy > 0.f ? hy : expm1f(hy);
    float2 hv = make_float2(hx, hy);
    *((float2*)(g_h1 + dst*HH) + lane) = hv;
    if (dst < TT)   // stash h1 row as last 64 cols of A (root2 term of conv2)
        *((float2*)(g_A + dst*KDIM + RR*HH) + lane) = hv;
}

// ---------------- K5: conv2 aggregation — per-relation runs (edges are rel-sorted) ----------------
__global__ void __launch_bounds__(256) k_conv2agg() {
    int lane = threadIdx.x & 31;
    int dst = blockIdx.x*8 + (threadIdx.x >> 5);   // grid sized so dst < TT exactly

    int cnt = 0;
    float inv = 1.0f;
    if (lane < RR) {
        cnt = g_cnt[dst*RR + lane];
        inv = 1.0f / (float)max(cnt, 1);
    }

    int ptr = g_off[dst];
    #pragma unroll
    for (int r = 0; r < RR; r++) {
        int   c = __shfl_sync(0xffffffffu, cnt, r);
        float s = __shfl_sync(0xffffffffu, inv, r);
        float2 sum = make_float2(0.f, 0.f);
        int i = 0;
        for (; i + 4 <= c; i += 4) {
            unsigned u[4];
            #pragma unroll
            for (int j = 0; j < 4; j++) u[j] = g_sorted[ptr + i + j];
            float2 hv[4];
            #pragma unroll
            for (int j = 0; j < 4; j++)
                hv[j] = *((const float2*)(g_h1 + (int)(u[j] & 0xffffu)*HH) + lane);
            #pragma unroll
            for (int j = 0; j < 4; j++) { sum.x += hv[j].x; sum.y += hv[j].y; }
        }
        for (; i < c; i++) {
            unsigned u = g_sorted[ptr + i];
            float2 h = *((const float2*)(g_h1 + (int)(u & 0xffffu)*HH) + lane);
            sum.x += h.x; sum.y += h.y;
        }
        ptr += c;
        *((float2*)(g_A + dst*KDIM + r*HH) + lane) = make_float2(sum.x*s, sum.y*s);
    }
}

// ---------------- K6: fused h2 = elu(A @ [w2;root2] + b2), out = h2 @ lin_w + lin_b ----------------
__global__ void __launch_bounds__(256) k_gemm(const float* __restrict__ w2,
                                              const float* __restrict__ root2,
                                              const float* __restrict__ bias2,
                                              const float* __restrict__ lw,
                                              const float* __restrict__ lb,
                                              float* __restrict__ out) {
    __shared__ float sA[64][33];       // A[m][k]
    __shared__ float sB[32*64];        // B[k][n], stride 64
    __shared__ float sH[64][65];       // h2 tile
    __shared__ float sW[HH*CC];        // lin_w
    int tid = threadIdx.x;
    int tx = tid & 15;                 // n dir: 4 cols each -> 64
    int ty = tid >> 4;                 // m dir: 4 rows each -> 64
    int m0 = blockIdx.x * 64;

    // preload lin_w (consumed after the k-loop; first __syncthreads covers it)
    *(float4*)&sW[tid*4] = *(const float4*)(lw + tid*4);

    float acc[4][4] = {};

    for (int kk0 = 0; kk0 < KDIM; kk0 += 32) {
        #pragma unroll
        for (int rep = 0; rep < 2; rep++) {
            int id = tid + rep*256;
            int row = id >> 3;             // 0..63
            int q = id & 7;                // 0..7
            float4 v = *(const float4*)(g_A + (m0 + row)*KDIM + kk0 + q*4);
            sA[row][q*4+0] = v.x; sA[row][q*4+1] = v.y;
            sA[row][q*4+2] = v.z; sA[row][q*4+3] = v.w;
        }
        #pragma unroll
        for (int rep = 0; rep < 2; rep++) {
            int id = tid + rep*256;
            int krow = id >> 4;            // 0..31
            int q = id & 15;               // 0..15
            int kk = kk0 + krow;
            const float* brow = (kk < RR*HH) ? (w2 + kk*HH) : (root2 + (kk - RR*HH)*HH);
            *(float4*)&sB[krow*64 + q*4] = *(const float4*)(brow + q*4);
        }
        __syncthreads();
        #pragma unroll
        for (int k = 0; k < 32; k++) {
            float a0 = sA[ty*4+0][k];
            float a1 = sA[ty*4+1][k];
            float a2 = sA[ty*4+2][k];
            float a3 = sA[ty*4+3][k];
            float4 b = *(const float4*)&sB[k*64 + tx*4];
            acc[0][0] = fmaf(a0,b.x,acc[0][0]); acc[0][1] = fmaf(a0,b.y,acc[0][1]);
            acc[0][2] = fmaf(a0,b.z,acc[0][2]); acc[0][3] = fmaf(a0,b.w,acc[0][3]);
            acc[1][0] = fmaf(a1,b.x,acc[1][0]); acc[1][1] = fmaf(a1,b.y,acc[1][1]);
            acc[1][2] = fmaf(a1,b.z,acc[1][2]); acc[1][3] = fmaf(a1,b.w,acc[1][3]);
            acc[2][0] = fmaf(a2,b.x,acc[2][0]); acc[2][1] = fmaf(a2,b.y,acc[2][1]);
            acc[2][2] = fmaf(a2,b.z,acc[2][2]); acc[2][3] = fmaf(a2,b.w,acc[2][3]);
            acc[3][0] = fmaf(a3,b.x,acc[3][0]); acc[3][1] = fmaf(a3,b.y,acc[3][1]);
            acc[3][2] = fmaf(a3,b.z,acc[3][2]); acc[3][3] = fmaf(a3,b.w,acc[3][3]);
        }
        __syncthreads();
    }

    // bias + elu into sH
    float4 bb = *(const float4*)(bias2 + tx*4);
    #pragma unroll
    for (int i = 0; i < 4; i++) {
        float v0 = acc[i][0] + bb.x;
        float v1 = acc[i][1] + bb.y;
        float v2 = acc[i][2] + bb.z;
        float v3 = acc[i][3] + bb.w;
        v0 = v0 > 0.f ? v0 : expm1f(v0);
        v1 = v1 > 0.f ? v1 : expm1f(v1);
        v2 = v2 > 0.f ? v2 : expm1f(v2);
        v3 = v3 > 0.f ? v3 : expm1f(v3);
        sH[ty*4+i][tx*4+0] = v0;
        sH[ty*4+i][tx*4+1] = v1;
        sH[ty*4+i][tx*4+2] = v2;
        sH[ty*4+i][tx*4+3] = v3;
    }
    __syncthreads();

    // head: out[m0+r, c] = sum_k sH[r][k] * lin_w[k][c] + lin_b[c]
    int r = tid >> 2;                  // 0..63
    int c0 = (tid & 3) * 4;            // 0,4,8,12
    float4 lbv = *(const float4*)(lb + c0);
    float s0 = lbv.x, s1 = lbv.y, s2 = lbv.z, s3 = lbv.w;
    #pragma unroll
    for (int k = 0; k < HH; k++) {
        float h = sH[r][k];
        float4 w = *(const float4*)&sW[k*CC + c0];
        s0 = fmaf(h, w.x, s0);
        s1 = fmaf(h, w.y, s1);
        s2 = fmaf(h, w.z, s2);
        s3 = fmaf(h, w.w, s3);
    }
    *(float4*)(out + (m0 + r)*CC + c0) = make_float4(s0, s1, s2, s3);
}

// ---------------- launcher ----------------
extern "C" void kernel_launch(void* const* d_in, const int* in_sizes, int n_in,
                              void* d_out, int out_size) {
    const int*   ei    = (const int*)d_in[0];    // edge_index [2,E]
    const int*   et    = (const int*)d_in[1];    // edge_type [E]
    // d_in[2] = num_target (shape known statically; out_size confirms T*C)
    const float* w1    = (const float*)d_in[3];  // [R,N,H]
    const float* root1 = (const float*)d_in[4];  // [N,H]
    const float* b1    = (const float*)d_in[5];  // [H]
    const float* w2    = (const float*)d_in[6];  // [R,H,H]
    const float* root2 = (const float*)d_in[7];  // [H,H]
    const float* b2    = (const float*)d_in[8];  // [H]
    const float* lw    = (const float*)d_in[9];  // [H,C]
    const float* lb    = (const float*)d_in[10]; // [C]
    float* out = (float*)d_out;
    (void)in_sizes; (void)n_in; (void)out_size;

    k_zero    <<<(NN*RR/4 + 255)/256, 256>>>();
    k_hist    <<<(EE/4 + 255)/256,    256>>>(ei, et);
    k_offsets <<<(NN + 255)/256,      256>>>();
    k_scatter <<<(EE/4 + 255)/256,    256>>>(ei, et);
    k_conv1   <<<(NN + 7)/8,          256>>>(w1, root1, b1);
    k_conv2agg<<<TT/8,                256>>>();
    k_gemm    <<<TT/64,               256>>>(w2, root2, b2, lw, lb, out);
}

// round 17
// speedup vs baseline: 1.3022x; 1.0035x over previous
#include <cuda_runtime.h>

// Problem constants (fixed by the dataset)
#define NN   50000
#define RR   8
#define HH   64
#define CC   16
#define EE   1600000
#define TT   8192
#define KDIM (RR*HH + HH)   // 576: 8 relation-aggregates + h1 (for root2)

// ---------------- device scratch (no allocations allowed) ----------------
__device__ int      g_cnt[NN*RR];        // edges per (dst, rel)
__device__ int      g_off[NN];           // start offset of dst's segment
__device__ int      g_off2[NN*RR];       // cursor: start offset of each (dst, rel) sub-segment
__device__ int      g_ctr;               // global offset reservation counter
__device__ unsigned g_sorted[EE];        // (rel<<16)|src, grouped by (dst, rel)
__device__ float    g_h1[NN*HH];         // conv1 output
__device__ float    g_A[TT*KDIM];        // conv2 LHS: [acc_r0..acc_r7 | h1]

// ---------------- K0: zero counters ----------------
__global__ void k_zero() {
    int i = blockIdx.x*blockDim.x + threadIdx.x;
    if (i*4 < NN*RR) ((int4*)g_cnt)[i] = make_int4(0,0,0,0);
    if (i == 0) g_ctr = 0;
}

// ---------------- K1: pure histogram per (dst, rel) — fire-and-forget RED ----------------
__global__ void __launch_bounds__(256) k_hist(const int* __restrict__ ei,
                                              const int* __restrict__ et) {
    int e4 = (blockIdx.x*blockDim.x + threadIdx.x) * 4;
    if (e4 >= EE) return;
    int4 d = __ldcs((const int4*)(ei + EE + e4));
    int4 r = __ldcs((const int4*)(et + e4));
    atomicAdd(&g_cnt[d.x*RR + r.x], 1);   // result unused -> RED (no return latency)
    atomicAdd(&g_cnt[d.y*RR + r.y], 1);
    atomicAdd(&g_cnt[d.z*RR + r.z], 1);
    atomicAdd(&g_cnt[d.w*RR + r.w], 1);
}

// ---------------- K2: reserve contiguous segment per dst + per-rel sub-cursors ----------------
__global__ void k_offsets() {
    int v = blockIdx.x*blockDim.x + threadIdx.x;
    int lane = threadIdx.x & 31;
    int cnt[RR];
    int deg = 0;
    if (v < NN) {
        int4 a = *(const int4*)&g_cnt[v*RR];
        int4 b = *(const int4*)&g_cnt[v*RR + 4];
        cnt[0]=a.x; cnt[1]=a.y; cnt[2]=a.z; cnt[3]=a.w;
        cnt[4]=b.x; cnt[5]=b.y; cnt[6]=b.z; cnt[7]=b.w;
        #pragma unroll
        for (int r = 0; r < RR; r++) deg += cnt[r];
    }
    // warp inclusive scan
    int x = deg;
    #pragma unroll
    for (int d = 1; d < 32; d <<= 1) {
        int y = __shfl_up_sync(0xffffffffu, x, d);
        if (lane >= d) x += y;
    }
    int total = __shfl_sync(0xffffffffu, x, 31);
    int base = 0;
    if (lane == 31) base = atomicAdd(&g_ctr, total);
    base = __shfl_sync(0xffffffffu, base, 31);
    if (v < NN) {
        int off = base + x - deg;
        g_off[v] = off;
        int p = off;
        #pragma unroll
        for (int r = 0; r < RR; r++) { g_off2[v*RR + r] = p; p += cnt[r]; }
    }
}

// ---------------- K3: scatter edges via atomic cursor (single pass, 12 B/edge in) ----------------
__global__ void __launch_bounds__(256) k_scatter(const int* __restrict__ ei,
                                                 const int* __restrict__ et) {
    int e4 = (blockIdx.x*blockDim.x + threadIdx.x) * 4;
    if (e4 >= EE) return;
    int4 s = __ldcs((const int4*)(ei + e4));
    int4 d = __ldcs((const int4*)(ei + EE + e4));
    int4 r = __ldcs((const int4*)(et + e4));
    int seg[4] = {d.x*RR + r.x, d.y*RR + r.y, d.z*RR + r.z, d.w*RR + r.w};
    int pos[4];
    #pragma unroll
    for (int j = 0; j < 4; j++) pos[j] = atomicAdd(&g_off2[seg[j]], 1);
    g_sorted[pos[0]] = ((unsigned)r.x << 16) | (unsigned)s.x;
    g_sorted[pos[1]] = ((unsigned)r.y << 16) | (unsigned)s.y;
    g_sorted[pos[2]] = ((unsigned)r.z << 16) | (unsigned)s.z;
    g_sorted[pos[3]] = ((unsigned)r.w << 16) | (unsigned)s.w;
}

// ---------------- K4: conv1 — warp per dst, gather weight1 rows (unroll 8) ----------------
__global__ void __launch_bounds__(256) k_conv1(const float* __restrict__ w1,
                                               const float* __restrict__ root1,
                                               const float* __restrict__ bias1) {
    __shared__ float sInv[8][RR];
    int warp = threadIdx.x >> 5;
    int lane = threadIdx.x & 31;
    int dst = blockIdx.x*8 + warp;
    if (dst >= NN) return;

    int c = 0;
    if (lane < RR) {
        c = g_cnt[dst*RR + lane];
        sInv[warp][lane] = 1.0f / (float)max(c, 1);
    }
    int d = (lane < RR) ? c : 0;
    #pragma unroll
    for (int s = 16; s; s >>= 1) d += __shfl_xor_sync(0xffffffffu, d, s);
    int deg = d;
    __syncwarp();

    int off = g_off[dst];
    float2 acc = make_float2(0.f, 0.f);
    int i = 0;
    for (; i + 8 <= deg; i += 8) {
        unsigned u[8];
        #pragma unroll
        for (int j = 0; j < 8; j++) u[j] = g_sorted[off + i + j];
        float2 wv[8];
        #pragma unroll
        for (int j = 0; j < 8; j++) {
            int rel = (int)(u[j] >> 16), src = (int)(u[j] & 0xffffu);
            wv[j] = *((const float2*)(w1 + rel*(NN*HH) + src*HH) + lane);
        }
        #pragma unroll
        for (int j = 0; j < 8; j++) {
            float s = sInv[warp][u[j] >> 16];
            acc.x = fmaf(s, wv[j].x, acc.x);
            acc.y = fmaf(s, wv[j].y, acc.y);
        }
    }
    if (i + 4 <= deg) {
        unsigned u[4];
        #pragma unroll
        for (int j = 0; j < 4; j++) u[j] = g_sorted[off + i + j];
        float2 wv[4];
        #pragma unroll
        for (int j = 0; j < 4; j++) {
            int rel = (int)(u[j] >> 16), src = (int)(u[j] & 0xffffu);
            wv[j] = *((const float2*)(w1 + rel*(NN*HH) + src*HH) + lane);
        }
        #pragma unroll
        for (int j = 0; j < 4; j++) {
            float s = sInv[warp][u[j] >> 16];
            acc.x = fmaf(s, wv[j].x, acc.x);
            acc.y = fmaf(s, wv[j].y, acc.y);
        }
        i += 4;
    }
    for (; i < deg; i++) {
        unsigned u = g_sorted[off + i];
        int rel = (int)(u >> 16), src = (int)(u & 0xffffu);
        float2 wv = *((const float2*)(w1 + rel*(NN*HH) + src*HH) + lane);
        float s = sInv[warp][rel];
        acc.x = fmaf(s, wv.x, acc.x);
        acc.y = fmaf(s, wv.y, acc.y);
    }

    float2 rt = *((const float2*)(root1 + dst*HH) + lane);
    float2 bb = *((const float2*)bias1 + lane);
    float hx = acc.x + rt.x + bb.x;
    float hy = acc.y + rt.y + bb.y;
    hx = hx > 0.f ? hx : expm1f(hx);
    hy = hy > 0.f ? hy : expm1f(hy);
    float2 hv = make_float2(hx, hy);
    *((float2*)(g_h1 + dst*HH) + lane) = hv;
    if (dst < TT)   // stash h1 row as last 64 cols of A (root2 term of conv2)
        *((float2*)(g_A + dst*KDIM + RR*HH) + lane) = hv;
}

// ---------------- K5: conv2 aggregation — per-relation runs (edges are rel-sorted) ----------------
__global__ void __launch_bounds__(256) k_conv2agg() {
    int lane = threadIdx.x & 31;
    int dst = blockIdx.x*8 + (threadIdx.x >> 5);   // grid sized so dst < TT exactly

    int cnt = 0;
    float inv = 1.0f;
    if (lane < RR) {
        cnt = g_cnt[dst*RR + lane];
        inv = 1.0f / (float)max(cnt, 1);
    }

    int ptr = g_off[dst];
    #pragma unroll
    for (int r = 0; r < RR; r++) {
        int   c = __shfl_sync(0xffffffffu, cnt, r);
        float s = __shfl_sync(0xffffffffu, inv, r);
        float2 sum = make_float2(0.f, 0.f);
        int i = 0;
        for (; i + 4 <= c; i += 4) {
            unsigned u[4];
            #pragma unroll
            for (int j = 0; j < 4; j++) u[j] = g_sorted[ptr + i + j];
            float2 hv[4];
            #pragma unroll
            for (int j = 0; j < 4; j++)
                hv[j] = *((const float2*)(g_h1 + (int)(u[j] & 0xffffu)*HH) + lane);
            #pragma unroll
            for (int j = 0; j < 4; j++) { sum.x += hv[j].x; sum.y += hv[j].y; }
        }
        for (; i < c; i++) {
            unsigned u = g_sorted[ptr + i];
            float2 h = *((const float2*)(g_h1 + (int)(u & 0xffffu)*HH) + lane);
            sum.x += h.x; sum.y += h.y;
        }
        ptr += c;
        *((float2*)(g_A + dst*KDIM + r*HH) + lane) = make_float2(sum.x*s, sum.y*s);
    }
}

// ---------------- K6: fused h2 = elu(A @ [w2;root2] + b2), out = h2 @ lin_w + lin_b ----------------
__global__ void __launch_bounds__(256) k_gemm(const float* __restrict__ w2,
                                              const float* __restrict__ root2,
                                              const float* __restrict__ bias2,
                                              const float* __restrict__ lw,
                                              const float* __restrict__ lb,
                                              float* __restrict__ out) {
    __shared__ float sA[64][33];       // A[m][k]
    __shared__ float sB[32*64];        // B[k][n], stride 64
    __shared__ float sH[64][65];       // h2 tile
    __shared__ float sW[HH*CC];        // lin_w
    int tid = threadIdx.x;
    int tx = tid & 15;                 // n dir: 4 cols each -> 64
    int ty = tid >> 4;                 // m dir: 4 rows each -> 64
    int m0 = blockIdx.x * 64;

    // preload lin_w (consumed after the k-loop; first __syncthreads covers it)
    *(float4*)&sW[tid*4] = *(const float4*)(lw + tid*4);

    float acc[4][4] = {};

    for (int kk0 = 0; kk0 < KDIM; kk0 += 32) {
        #pragma unroll
        for (int rep = 0; rep < 2; rep++) {
            int id = tid + rep*256;
            int row = id >> 3;             // 0..63
            int q = id & 7;                // 0..7
            float4 v = *(const float4*)(g_A + (m0 + row)*KDIM + kk0 + q*4);
            sA[row][q*4+0] = v.x; sA[row][q*4+1] = v.y;
            sA[row][q*4+2] = v.z; sA[row][q*4+3] = v.w;
        }
        #pragma unroll
        for (int rep = 0; rep < 2; rep++) {
            int id = tid + rep*256;
            int krow = id >> 4;            // 0..31
            int q = id & 15;               // 0..15
            int kk = kk0 + krow;
            const float* brow = (kk < RR*HH) ? (w2 + kk*HH) : (root2 + (kk - RR*HH)*HH);
            *(float4*)&sB[krow*64 + q*4] = *(const float4*)(brow + q*4);
        }
        __syncthreads();
        #pragma unroll
        for (int k = 0; k < 32; k++) {
            float a0 = sA[ty*4+0][k];
            float a1 = sA[ty*4+1][k];
            float a2 = sA[ty*4+2][k];
            float a3 = sA[ty*4+3][k];
            float4 b = *(const float4*)&sB[k*64 + tx*4];
            acc[0][0] = fmaf(a0,b.x,acc[0][0]); acc[0][1] = fmaf(a0,b.y,acc[0][1]);
            acc[0][2] = fmaf(a0,b.z,acc[0][2]); acc[0][3] = fmaf(a0,b.w,acc[0][3]);
            acc[1][0] = fmaf(a1,b.x,acc[1][0]); acc[1][1] = fmaf(a1,b.y,acc[1][1]);
            acc[1][2] = fmaf(a1,b.z,acc[1][2]); acc[1][3] = fmaf(a1,b.w,acc[1][3]);
            acc[2][0] = fmaf(a2,b.x,acc[2][0]); acc[2][1] = fmaf(a2,b.y,acc[2][1]);
            acc[2][2] = fmaf(a2,b.z,acc[2][2]); acc[2][3] = fmaf(a2,b.w,acc[2][3]);
            acc[3][0] = fmaf(a3,b.x,acc[3][0]); acc[3][1] = fmaf(a3,b.y,acc[3][1]);
            acc[3][2] = fmaf(a3,b.z,acc[3][2]); acc[3][3] = fmaf(a3,b.w,acc[3][3]);
        }
        __syncthreads();
    }

    // bias + elu into sH
    float4 bb = *(const float4*)(bias2 + tx*4);
    #pragma unroll
    for (int i = 0; i < 4; i++) {
        float v0 = acc[i][0] + bb.x;
        float v1 = acc[i][1] + bb.y;
        float v2 = acc[i][2] + bb.z;
        float v3 = acc[i][3] + bb.w;
        v0 = v0 > 0.f ? v0 : expm1f(v0);
        v1 = v1 > 0.f ? v1 : expm1f(v1);
        v2 = v2 > 0.f ? v2 : expm1f(v2);
        v3 = v3 > 0.f ? v3 : expm1f(v3);
        sH[ty*4+i][tx*4+0] = v0;
        sH[ty*4+i][tx*4+1] = v1;
        sH[ty*4+i][tx*4+2] = v2;
        sH[ty*4+i][tx*4+3] = v3;
    }
    __syncthreads();

    // head: out[m0+r, c] = sum_k sH[r][k] * lin_w[k][c] + lin_b[c]
    int r = tid >> 2;                  // 0..63
    int c0 = (tid & 3) * 4;            // 0,4,8,12
    float4 lbv = *(const float4*)(lb + c0);
    float s0 = lbv.x, s1 = lbv.y, s2 = lbv.z, s3 = lbv.w;
    #pragma unroll
    for (int k = 0; k < HH; k++) {
        float h = sH[r][k];
        float4 w = *(const float4*)&sW[k*CC + c0];
        s0 = fmaf(h, w.x, s0);
        s1 = fmaf(h, w.y, s1);
        s2 = fmaf(h, w.z, s2);
        s3 = fmaf(h, w.w, s3);
    }
    *(float4*)(out + (m0 + r)*CC + c0) = make_float4(s0, s1, s2, s3);
}

// ---------------- launcher ----------------
extern "C" void kernel_launch(void* const* d_in, const int* in_sizes, int n_in,
                              void* d_out, int out_size) {
    const int*   ei    = (const int*)d_in[0];    // edge_index [2,E]
    const int*   et    = (const int*)d_in[1];    // edge_type [E]
    // d_in[2] = num_target (shape known statically; out_size confirms T*C)
    const float* w1    = (const float*)d_in[3];  // [R,N,H]
    const float* root1 = (const float*)d_in[4];  // [N,H]
    const float* b1    = (const float*)d_in[5];  // [H]
    const float* w2    = (const float*)d_in[6];  // [R,H,H]
    const float* root2 = (const float*)d_in[7];  // [H,H]
    const float* b2    = (const float*)d_in[8];  // [H]
    const float* lw    = (const float*)d_in[9];  // [H,C]
    const float* lb    = (const float*)d_in[10]; // [C]
    float* out = (float*)d_out;
    (void)in_sizes; (void)n_in; (void)out_size;

    k_zero    <<<(NN*RR/4 + 255)/256, 256>>>();
    k_hist    <<<(EE/4 + 255)/256,    256>>>(ei, et);
    k_offsets <<<(NN + 255)/256,      256>>>();
    k_scatter <<<(EE/4 + 255)/256,    256>>>(ei, et);
    k_conv1   <<<(NN + 7)/8,          256>>>(w1, root1, b1);
    k_conv2agg<<<TT/8,                256>>>();
    k_gemm    <<<TT/64,               256>>>(w2, root2, b2, lw, lb, out);
}